// round 15
// baseline (speedup 1.0000x reference)
#include <cuda_runtime.h>
#include <cuda_bf16.h>
#include <cuda_fp16.h>
#include <cstdint>
#include <math.h>

#define B_   2
#define T_   1024
#define D_   6144
#define NQ_  48
#define NKV_ 8
#define HD_  128
#define GQ_  (NQ_ / NKV_)
#define MULT_     0.08838834764831845f
#define MAX_ATTN_ 30.0f
#define M_ROWS (B_ * T_)           // 2048
#define NQKV   (NQ_ * HD_ + 2 * NKV_ * HD_)   // 8192 -> 64 n-blocks of 128
#define KBLK0  NQ_
#define VBLK0  (NQ_ + NKV_)

// ---------------- scratch (__device__ globals; no allocation) ----------------
__device__ float2 g_rope[T_ * 64];

__device__ __nv_bfloat16 g_xq_hi[(size_t)M_ROWS * D_];
__device__ __nv_bfloat16 g_xq_lo[(size_t)M_ROWS * D_];
__device__ __nv_bfloat16 g_xk_hi[(size_t)M_ROWS * D_];
__device__ __nv_bfloat16 g_xk_lo[(size_t)M_ROWS * D_];
__device__ __nv_bfloat16 g_xv_hi[(size_t)M_ROWS * D_];
__device__ __nv_bfloat16 g_xv_lo[(size_t)M_ROWS * D_];
__device__ __nv_bfloat16 g_wt_hi[(size_t)NQKV * D_];
__device__ __nv_bfloat16 g_wt_lo[(size_t)NQKV * D_];
__device__ __nv_bfloat16 g_qh[(size_t)M_ROWS * NQ_ * HD_];
__device__ __nv_bfloat16 g_ql[(size_t)M_ROWS * NQ_ * HD_];
__device__ __nv_bfloat16 g_kh[(size_t)M_ROWS * NKV_ * HD_];
__device__ __nv_bfloat16 g_kl[(size_t)M_ROWS * NKV_ * HD_];
__device__ __nv_bfloat16 g_vh[(size_t)M_ROWS * NKV_ * HD_];
__device__ __nv_bfloat16 g_vl[(size_t)M_ROWS * NKV_ * HD_];

// ---------------- rope table ----------------
__global__ void rope_table_kernel() {
    const int i = blockIdx.x * blockDim.x + threadIdx.x;
    const int t = i >> 6, j = i & 63;
    const double invf = exp(-log(10000.0) * (double)j / 64.0);
    double ph = (double)t * invf;
    const double twopi = 6.283185307179586476925286766559;
    ph -= twopi * floor(ph / twopi);
    float s, c;
    sincosf((float)ph, &s, &c);
    g_rope[i] = make_float2(c, s);
}

// ---------------- fp32 -> (hi, lo) fp16 split, 3 tensors ----------------
__global__ __launch_bounds__(256) void conv_split3_f16_kernel(
    const float* __restrict__ x0, const float* __restrict__ x1, const float* __restrict__ x2,
    __half* __restrict__ h0p, __half* __restrict__ l0p,
    __half* __restrict__ h1p, __half* __restrict__ l1p,
    __half* __restrict__ h2p, __half* __restrict__ l2p, int n4)
{
    const int i = blockIdx.x * blockDim.x + threadIdx.x;
    if (i >= n4) return;
    const float* x = (blockIdx.y == 0) ? x0 : (blockIdx.y == 1) ? x1 : x2;
    __half* hi = (blockIdx.y == 0) ? h0p : (blockIdx.y == 1) ? h1p : h2p;
    __half* lo = (blockIdx.y == 0) ? l0p : (blockIdx.y == 1) ? l1p : l2p;
    const float4 v = ((const float4*)x)[i];
    const __half h0 = __float2half_rn(v.x);
    const __half h1 = __float2half_rn(v.y);
    const __half h2 = __float2half_rn(v.z);
    const __half h3 = __float2half_rn(v.w);
    __half2* H = (__half2*)hi;
    __half2* L = (__half2*)lo;
    H[2 * i]     = __half2(h0, h1);
    H[2 * i + 1] = __half2(h2, h3);
    L[2 * i]     = __half2(__float2half_rn(v.x - __half2float(h0)),
                           __float2half_rn(v.y - __half2float(h1)));
    L[2 * i + 1] = __half2(__float2half_rn(v.z - __half2float(h2)),
                           __float2half_rn(v.w - __half2float(h3)));
}

// ---------------- W[K,N] fp32 -> Wt[N,K] fp16, row offset ----------------
__global__ void transpose_half_kernel(
    const float* __restrict__ W, __half* __restrict__ Th, int K, int N, int row_off)
{
    __shared__ float s[32][33];
    const int k0 = blockIdx.y * 32, n0 = blockIdx.x * 32;
    const int tx = threadIdx.x, ty = threadIdx.y;
    #pragma unroll
    for (int i = 0; i < 4; i++)
        s[ty + 8 * i][tx] = W[(size_t)(k0 + ty + 8 * i) * N + n0 + tx];
    __syncthreads();
    #pragma unroll
    for (int i = 0; i < 4; i++)
        Th[(size_t)(row_off + n0 + ty + 8 * i) * K + k0 + tx] =
            __float2half_rn(s[tx][ty + 8 * i]);
}

// ---------------- common MMA helpers ----------------
__device__ __forceinline__ uint32_t smem_u32(const void* p) {
    uint32_t a;
    asm("{ .reg .u64 t; cvta.to.shared.u64 t, %1; cvt.u32.u64 %0, t; }" : "=r"(a) : "l"(p));
    return a;
}
__device__ __forceinline__ void cp16(uint32_t dst, const void* src) {
    asm volatile("cp.async.cg.shared.global [%0], [%1], 16;" :: "r"(dst), "l"(src));
}
__device__ __forceinline__ void mma_bf16(float* c, const uint32_t* a, const uint32_t* b) {
    asm volatile(
        "mma.sync.aligned.m16n8k16.row.col.f32.bf16.bf16.f32 "
        "{%0,%1,%2,%3}, {%4,%5,%6,%7}, {%8,%9}, {%0,%1,%2,%3};"
        : "+f"(c[0]), "+f"(c[1]), "+f"(c[2]), "+f"(c[3])
        : "r"(a[0]), "r"(a[1]), "r"(a[2]), "r"(a[3]), "r"(b[0]), "r"(b[1]));
}
__device__ __forceinline__ void mma_f16(float* c, const uint32_t* a, const uint32_t* b) {
    asm volatile(
        "mma.sync.aligned.m16n8k16.row.col.f32.f16.f16.f32 "
        "{%0,%1,%2,%3}, {%4,%5,%6,%7}, {%8,%9}, {%0,%1,%2,%3};"
        : "+f"(c[0]), "+f"(c[1]), "+f"(c[2]), "+f"(c[3])
        : "r"(a[0]), "r"(a[1]), "r"(a[2]), "r"(a[3]), "r"(b[0]), "r"(b[1]));
}
__device__ __forceinline__ void ldsm_x4(uint32_t* r, uint32_t addr) {
    asm volatile("ldmatrix.sync.aligned.m8n8.x4.shared.b16 {%0,%1,%2,%3}, [%4];"
        : "=r"(r[0]), "=r"(r[1]), "=r"(r[2]), "=r"(r[3]) : "r"(addr));
}
__device__ __forceinline__ void ldsm_x4t(uint32_t* r, uint32_t addr) {
    asm volatile("ldmatrix.sync.aligned.m8n8.x4.trans.shared.b16 {%0,%1,%2,%3}, [%4];"
        : "=r"(r[0]), "=r"(r[1]), "=r"(r[2]), "=r"(r[3]) : "r"(addr));
}
__device__ __forceinline__ uint32_t pack_hi(float a, float b) {
    __nv_bfloat162 t(__float2bfloat16_rn(a), __float2bfloat16_rn(b));
    return *(uint32_t*)&t;
}
__device__ __forceinline__ uint32_t pack_lo(float a, float b, uint32_t hi) {
    __nv_bfloat162 h = *(__nv_bfloat162*)&hi;
    __nv_bfloat162 t(__float2bfloat16_rn(a - __bfloat162float(h.x)),
                     __float2bfloat16_rn(b - __bfloat162float(h.y)));
    return *(uint32_t*)&t;
}

#define PITCH_E   40
#define TILE_E    (128 * PITCH_E)             // 5120 halfs / 10240 B
#define QSTAGE_E  (3 * TILE_E)                // Ah, Al, B = 30720 B
#define QSMEM_BYTES (3 * QSTAGE_E * 2)        // 92160 B -> 2 CTAs/SM

// ---------------- fp16 2-term mainloop, 3-stage (R10-proven sync pattern) ---
__device__ __forceinline__ void gemm_mainloop_2t(
    const __half* __restrict__ Ah_g, const __half* __restrict__ Al_g,
    const __half* __restrict__ B_g, int K, uint32_t sb, float acc[4][4][4])
{
    const int tid  = threadIdx.x;
    const int wid  = tid >> 5, lane = tid & 31;
    const int wm   = wid >> 2;
    const int wn   = wid & 3;
    const int a_row = ((lane >> 3) & 1) * 8 + (lane & 7);
    const int a_col = (lane >> 4) * 8;
    const int b_row = ((lane >> 4) & 1) * 8 + (lane & 7);
    const int b_col = ((lane >> 3) & 1) * 8;

    const __half* srcs[3] = { Ah_g, Al_g, B_g };
    const int nk = K / 32;

    auto load_chunk = [&](int c, int s) {
        const uint32_t sbase = sb + s * (QSTAGE_E * 2);
        #pragma unroll
        for (int t = 0; t < 3; t++) {
            #pragma unroll
            for (int j = 0; j < 2; j++) {
                const int i   = tid + 256 * j;
                const int row = i >> 2;
                const int kc  = i & 3;
                cp16(sbase + t * (TILE_E * 2) + row * (PITCH_E * 2) + kc * 16,
                     srcs[t] + (size_t)row * K + c * 32 + kc * 8);
            }
        }
    };

    load_chunk(0, 0);
    asm volatile("cp.async.commit_group;");
    load_chunk(1, 1);
    asm volatile("cp.async.commit_group;");

    for (int c = 0; c < nk; c++) {
        if (c + 2 < nk) {
            __syncthreads();   // all warps done reading stage (c+2)%3 (chunk c-1)
            load_chunk(c + 2, (c + 2) % 3);
            asm volatile("cp.async.commit_group;");
            asm volatile("cp.async.wait_group 2;");
        } else if (c + 1 < nk) {
            asm volatile("cp.async.wait_group 1;");
        } else {
            asm volatile("cp.async.wait_group 0;");
        }
        __syncthreads();

        const uint32_t Ahb = sb + (c % 3) * (QSTAGE_E * 2);
        const uint32_t Alb = Ahb + TILE_E * 2;
        const uint32_t Bb  = Ahb + 2 * TILE_E * 2;

        #pragma unroll
        for (int ks = 0; ks < 2; ks++) {
            const int k16 = ks * 16;
            uint32_t ah[4][4], al[4][4], bf[4][2];
            #pragma unroll
            for (int mf = 0; mf < 4; mf++) {
                const uint32_t off =
                    ((wm * 64 + mf * 16 + a_row) * PITCH_E + k16 + a_col) * 2;
                ldsm_x4(ah[mf], Ahb + off);
                ldsm_x4(al[mf], Alb + off);
            }
            #pragma unroll
            for (int nfp = 0; nfp < 2; nfp++) {
                const uint32_t off =
                    ((wn * 32 + nfp * 16 + b_row) * PITCH_E + k16 + b_col) * 2;
                uint32_t r[4];
                ldsm_x4(r, Bb + off);
                bf[2 * nfp][0] = r[0]; bf[2 * nfp][1] = r[1];
                bf[2 * nfp + 1][0] = r[2]; bf[2 * nfp + 1][1] = r[3];
            }
            #pragma unroll
            for (int mf = 0; mf < 4; mf++)
                #pragma unroll
                for (int nf = 0; nf < 4; nf++) {
                    mma_f16(acc[mf][nf], ah[mf], bf[nf]);
                    mma_f16(acc[mf][nf], al[mf], bf[nf]);
                }
        }
    }
    __syncthreads();
}

// ---------------- merged QKV GEMM (fp16 2-term) + fused epilogue ------------
__global__ __launch_bounds__(256) void hmma_gemm_qkv_kernel(
    const __half* __restrict__ Xqh, const __half* __restrict__ Xql,
    const __half* __restrict__ Xkh, const __half* __restrict__ Xkl,
    const __half* __restrict__ Xvh, const __half* __restrict__ Xvl,
    const __half* __restrict__ Wt,
    const float* __restrict__ bq, const float* __restrict__ bk, const float* __restrict__ bv,
    __nv_bfloat16* __restrict__ qh, __nv_bfloat16* __restrict__ ql,
    __nv_bfloat16* __restrict__ kh, __nv_bfloat16* __restrict__ kl,
    __nv_bfloat16* __restrict__ vh, __nv_bfloat16* __restrict__ vl)
{
    extern __shared__ __half smh[];
    const uint32_t sb = smem_u32(smh);
    const int tid = threadIdx.x;
    const int wid = tid >> 5, lane = tid & 31;
    const int wm = wid >> 2, wn = wid & 3;
    const int gid = lane >> 2, tig = lane & 3;
    const int m0 = blockIdx.y * 128;
    const int jb = blockIdx.x;
    const int K  = D_;

    const int region = (jb < KBLK0) ? 0 : ((jb < VBLK0) ? 1 : 2);
    const __half* Ah_g = (region == 0) ? Xqh : (region == 1) ? Xkh : Xvh;
    const __half* Al_g = (region == 0) ? Xql : (region == 1) ? Xkl : Xvl;

    float acc[4][4][4];
    #pragma unroll
    for (int i = 0; i < 4; i++)
        #pragma unroll
        for (int j = 0; j < 4; j++)
            #pragma unroll
            for (int v = 0; v < 4; v++) acc[i][j][v] = 0.f;

    gemm_mainloop_2t(Ah_g + (size_t)m0 * K, Al_g + (size_t)m0 * K,
                     Wt + (size_t)jb * 128 * K, K, sb, acc);

    const int Nreg = (region == 0) ? NQ_ * HD_ : NKV_ * HD_;
    const int n0r  = (region == 0) ? jb * 128 : (region == 1) ? (jb - KBLK0) * 128
                                              : (jb - VBLK0) * 128;
    const float* bias = (region == 0) ? bq : (region == 1) ? bk : bv;
    __nv_bfloat16* Yh = (region == 0) ? qh : (region == 1) ? kh : vh;
    __nv_bfloat16* Yl = (region == 0) ? ql : (region == 1) ? kl : vl;

    float* sepi = (float*)smh;
    #pragma unroll
    for (int mf = 0; mf < 4; mf++) {
        const int r = wm * 64 + mf * 16 + gid;
        #pragma unroll
        for (int nf = 0; nf < 4; nf++) {
            const int col = wn * 32 + nf * 8 + 2 * tig;
            *(float2*)&sepi[r * 132 + col]       = make_float2(acc[mf][nf][0], acc[mf][nf][1]);
            *(float2*)&sepi[(r + 8) * 132 + col] = make_float2(acc[mf][nf][2], acc[mf][nf][3]);
        }
    }
    __syncthreads();
    const bool do_rope = (region < 2);
    #pragma unroll
    for (int it = 0; it < 16; it++) {
        const int idx = it * 256 + tid;
        const int r = idx >> 5, j = (idx & 31) * 2;
        const int t = (m0 + r) % T_;
        const float x1a = sepi[r * 132 + j]      + bias[n0r + j];
        const float x1b = sepi[r * 132 + j + 1]  + bias[n0r + j + 1];
        const float x2a = sepi[r * 132 + j + 64] + bias[n0r + j + 64];
        const float x2b = sepi[r * 132 + j + 65] + bias[n0r + j + 65];
        float o1a, o1b, o2a, o2b;
        if (do_rope) {
            const float2 cs0 = g_rope[t * 64 + j];
            const float2 cs1 = g_rope[t * 64 + j + 1];
            o1a = x1a * cs0.x - x2a * cs0.y;
            o1b = x1b * cs1.x - x2b * cs1.y;
            o2a = x2a * cs0.x + x1a * cs0.y;
            o2b = x2b * cs1.x + x1b * cs1.y;
        } else {
            o1a = x1a; o1b = x1b; o2a = x2a; o2b = x2b;
        }
        const size_t base = (size_t)(m0 + r) * Nreg + n0r;
        const uint32_t h1 = pack_hi(o1a, o1b), h2 = pack_hi(o2a, o2b);
        *(uint32_t*)&Yh[base + j]      = h1;
        *(uint32_t*)&Yh[base + j + 64] = h2;
        *(uint32_t*)&Yl[base + j]      = pack_lo(o1a, o1b, h1);
        *(uint32_t*)&Yl[base + j + 64] = pack_lo(o2a, o2b, h2);
    }
}

// ---------------- fp16 single-plane O-GEMM, 3-stage ----------------
#define OTILE_E   (128 * PITCH_E)
#define OSTAGE_E  (2 * OTILE_E)               // 20480 B
#define OSMEM_BYTES (3 * OSTAGE_E * 2)        // 61440 B -> 2 CTAs/SM

__global__ __launch_bounds__(256) void hmma_gemm_o_f16_kernel(
    const __half* __restrict__ X, const __half* __restrict__ W,
    float* __restrict__ Yf, int M, int N, int K)
{
    extern __shared__ __half smh[];
    const uint32_t sb = smem_u32(smh);
    const int tid = threadIdx.x;
    const int wid = tid >> 5, lane = tid & 31;
    const int wm = wid >> 2, wn = wid & 3;
    const int gid = lane >> 2, tig = lane & 3;
    const int m0 = blockIdx.y * 128;
    const int n0 = blockIdx.x * 128;
    const int a_row = ((lane >> 3) & 1) * 8 + (lane & 7);
    const int a_col = (lane >> 4) * 8;
    const int b_row = ((lane >> 4) & 1) * 8 + (lane & 7);
    const int b_col = ((lane >> 3) & 1) * 8;

    const __half* Ag = X + (size_t)m0 * K;
    const __half* Bg = W + (size_t)n0 * K;

    float acc[4][4][4];
    #pragma unroll
    for (int i = 0; i < 4; i++)
        #pragma unroll
        for (int j = 0; j < 4; j++)
            #pragma unroll
            for (int v = 0; v < 4; v++) acc[i][j][v] = 0.f;

    const int nk = K / 32;

    auto load_chunk = [&](int c, int s) {
        const uint32_t sbase = sb + s * (OSTAGE_E * 2);
        #pragma unroll
        for (int j = 0; j < 2; j++) {
            const int i = tid + 256 * j;
            const int row = i >> 2;
            const int kc = i & 3;
            const size_t goff = (size_t)row * K + c * 32 + kc * 8;
            const uint32_t soff = row * (PITCH_E * 2) + kc * 16;
            cp16(sbase + soff, Ag + goff);
            cp16(sbase + OTILE_E * 2 + soff, Bg + goff);
        }
    };

    load_chunk(0, 0);
    asm volatile("cp.async.commit_group;");
    load_chunk(1, 1);
    asm volatile("cp.async.commit_group;");

    for (int c = 0; c < nk; c++) {
        if (c + 2 < nk) {
            __syncthreads();
            load_chunk(c + 2, (c + 2) % 3);
            asm volatile("cp.async.commit_group;");
            asm volatile("cp.async.wait_group 2;");
        } else if (c + 1 < nk) {
            asm volatile("cp.async.wait_group 1;");
        } else {
            asm volatile("cp.async.wait_group 0;");
        }
        __syncthreads();

        const uint32_t Ab = sb + (c % 3) * (OSTAGE_E * 2);
        const uint32_t Bb = Ab + OTILE_E * 2;

        #pragma unroll
        for (int ks = 0; ks < 2; ks++) {
            const int k16 = ks * 16;
            uint32_t af[4][4], bf[4][2];
            #pragma unroll
            for (int mf = 0; mf < 4; mf++) {
                const uint32_t off =
                    ((wm * 64 + mf * 16 + a_row) * PITCH_E + k16 + a_col) * 2;
                ldsm_x4(af[mf], Ab + off);
            }
            #pragma unroll
            for (int nfp = 0; nfp < 2; nfp++) {
                const uint32_t off =
                    ((wn * 32 + nfp * 16 + b_row) * PITCH_E + k16 + b_col) * 2;
                uint32_t r[4];
                ldsm_x4(r, Bb + off);
                bf[2 * nfp][0] = r[0]; bf[2 * nfp][1] = r[1];
                bf[2 * nfp + 1][0] = r[2]; bf[2 * nfp + 1][1] = r[3];
            }
            #pragma unroll
            for (int mf = 0; mf < 4; mf++)
                #pragma unroll
                for (int nf = 0; nf < 4; nf++)
                    mma_f16(acc[mf][nf], af[mf], bf[nf]);
        }
    }

    #pragma unroll
    for (int mf = 0; mf < 4; mf++) {
        const int row = m0 + wm * 64 + mf * 16 + gid;
        #pragma unroll
        for (int nf = 0; nf < 4; nf++) {
            const int col = n0 + wn * 32 + nf * 8 + 2 * tig;
            *(float2*)&Yf[(size_t)row * N + col] =
                make_float2(acc[mf][nf][0], acc[mf][nf][1]);
            *(float2*)&Yf[(size_t)(row + 8) * N + col] =
                make_float2(acc[mf][nf][2], acc[mf][nf][3]);
        }
    }
}

// ---------------- HMMA attention (R13 verbatim: single-buffer K/V) ----------
#define AQ_P 136
#define ASMEM_BYTES ((2 * 128 + 4 * 64) * AQ_P * 2)   // 139264 B

__device__ __forceinline__ float softcap_exp(float s) {
    const float x = s * (MULT_ / MAX_ATTN_);
    const float e2 = __expf(2.f * x);
    const float cap = MAX_ATTN_ - __fdividef(2.f * MAX_ATTN_, e2 + 1.f);
    return __expf(cap);
}

__global__ __launch_bounds__(256) void attn_hmma_kernel(
    const __nv_bfloat16* __restrict__ gqh, const __nv_bfloat16* __restrict__ gql,
    const __nv_bfloat16* __restrict__ gkh, const __nv_bfloat16* __restrict__ gkl,
    const __nv_bfloat16* __restrict__ gvh, const __nv_bfloat16* __restrict__ gvl,
    __half* __restrict__ outp)
{
    extern __shared__ __nv_bfloat16 as2[];
    __nv_bfloat16* Qh  = as2;
    __nv_bfloat16* Ql  = Qh + 128 * AQ_P;
    __nv_bfloat16* Kh  = Ql + 128 * AQ_P;
    __nv_bfloat16* Kl  = Kh + 64 * AQ_P;
    __nv_bfloat16* Vh  = Kl + 64 * AQ_P;
    __nv_bfloat16* Vl  = Vh + 64 * AQ_P;
    const uint32_t sbA = smem_u32(as2);
    const uint32_t QhO = 0;
    const uint32_t QlO = 128 * AQ_P * 2;
    const uint32_t KhO = 2 * 128 * AQ_P * 2;
    const uint32_t KlO = KhO + 64 * AQ_P * 2;
    const uint32_t VhO = KlO + 64 * AQ_P * 2;
    const uint32_t VlO = VhO + 64 * AQ_P * 2;

    const int bh  = blockIdx.y;
    const int b   = bh / NQ_;
    const int h   = bh % NQ_;
    const int kvh = h / GQ_;
    const int q0  = blockIdx.x * 128;

    const int tid = threadIdx.x;
    const int wid = tid >> 5, lane = tid & 31;
    const int gid = lane >> 2, tig = lane & 3;
    const int a_row = ((lane >> 3) & 1) * 8 + (lane & 7);
    const int a_col = (lane >> 4) * 8;
    const int b_row = ((lane >> 4) & 1) * 8 + (lane & 7);
    const int b_col = ((lane >> 3) & 1) * 8;

    for (int i = tid; i < 128 * 16; i += 256) {
        const int row = i >> 4, c16 = (i & 15) * 8;
        const size_t src = ((size_t)(b * T_ + q0 + row)) * (NQ_ * HD_) + h * HD_ + c16;
        *(uint4*)&Qh[row * AQ_P + c16] = *(const uint4*)&gqh[src];
        *(uint4*)&Ql[row * AQ_P + c16] = *(const uint4*)&gql[src];
    }

    float oacc[16][4];
    #pragma unroll
    for (int n = 0; n < 16; n++)
        #pragma unroll
        for (int v = 0; v < 4; v++) oacc[n][v] = 0.f;
    float rs0 = 0.f, rs1 = 0.f;

    const int qg0 = q0 + wid * 16 + gid;
    const int qg1 = qg0 + 8;

    const int nkb = 2 * blockIdx.x + 2;
    for (int kb = 0; kb < nkb; kb++) {
        __syncthreads();
        for (int i = tid; i < 64 * 16; i += 256) {
            const int row = i >> 4, c16 = (i & 15) * 8;
            const size_t src = ((size_t)(b * T_ + kb * 64 + row)) * (NKV_ * HD_) + kvh * HD_ + c16;
            *(uint4*)&Kh[row * AQ_P + c16] = *(const uint4*)&gkh[src];
            *(uint4*)&Kl[row * AQ_P + c16] = *(const uint4*)&gkl[src];
            *(uint4*)&Vh[row * AQ_P + c16] = *(const uint4*)&gvh[src];
            *(uint4*)&Vl[row * AQ_P + c16] = *(const uint4*)&gvl[src];
        }
        __syncthreads();

        float sacc[8][4];
        #pragma unroll
        for (int nf = 0; nf < 8; nf++)
            #pragma unroll
            for (int v = 0; v < 4; v++) sacc[nf][v] = 0.f;

        #pragma unroll
        for (int ks = 0; ks < 8; ks++) {
            uint32_t ah[4], al[4];
            const uint32_t offa = ((wid * 16 + a_row) * AQ_P + ks * 16 + a_col) * 2;
            ldsm_x4(ah, sbA + QhO + offa);
            ldsm_x4(al, sbA + QlO + offa);
            #pragma unroll
            for (int g = 0; g < 4; g++) {
                const uint32_t offb = ((g * 16 + b_row) * AQ_P + ks * 16 + b_col) * 2;
                uint32_t rh[4], rl[4];
                ldsm_x4(rh, sbA + KhO + offb);
                ldsm_x4(rl, sbA + KlO + offb);
                mma_bf16(sacc[2 * g],     ah, rh);
                mma_bf16(sacc[2 * g],     ah, rl);
                mma_bf16(sacc[2 * g],     al, rh);
                mma_bf16(sacc[2 * g + 1], ah, rh + 2);
                mma_bf16(sacc[2 * g + 1], ah, rl + 2);
                mma_bf16(sacc[2 * g + 1], al, rh + 2);
            }
        }

        uint32_t ph[8][2], pl[8][2];
        #pragma unroll
        for (int nf = 0; nf < 8; nf++) {
            const int kg = kb * 64 + nf * 8 + tig * 2;
            float p0 = (kg     <= qg0) ? softcap_exp(sacc[nf][0]) : 0.f;
            float p1 = (kg + 1 <= qg0) ? softcap_exp(sacc[nf][1]) : 0.f;
            float p2 = (kg     <= qg1) ? softcap_exp(sacc[nf][2]) : 0.f;
            float p3 = (kg + 1 <= qg1) ? softcap_exp(sacc[nf][3]) : 0.f;
            rs0 += p0 + p1;
            rs1 += p2 + p3;
            ph[nf][0] = pack_hi(p0, p1);
            ph[nf][1] = pack_hi(p2, p3);
            pl[nf][0] = pack_lo(p0, p1, ph[nf][0]);
            pl[nf][1] = pack_lo(p2, p3, ph[nf][1]);
        }

        #pragma unroll
        for (int s = 0; s < 4; s++) {
            uint32_t ah2[4] = { ph[2 * s][0], ph[2 * s][1], ph[2 * s + 1][0], ph[2 * s + 1][1] };
            uint32_t al2[4] = { pl[2 * s][0], pl[2 * s][1], pl[2 * s + 1][0], pl[2 * s + 1][1] };
            #pragma unroll
            for (int g = 0; g < 8; g++) {
                const uint32_t offv = ((s * 16 + a_row) * AQ_P + g * 16 + a_col) * 2;
                uint32_t rh[4], rl[4];
                ldsm_x4t(rh, sbA + VhO + offv);
                ldsm_x4t(rl, sbA + VlO + offv);
                mma_bf16(oacc[2 * g],     ah2, rh);
                mma_bf16(oacc[2 * g],     ah2, rl);
                mma_bf16(oacc[2 * g],     al2, rh);
                mma_bf16(oacc[2 * g + 1], ah2, rh + 2);
                mma_bf16(oacc[2 * g + 1], ah2, rl + 2);
                mma_bf16(oacc[2 * g + 1], al2, rh + 2);
            }
        }
    }

    rs0 += __shfl_xor_sync(0xFFFFFFFFu, rs0, 1);
    rs0 += __shfl_xor_sync(0xFFFFFFFFu, rs0, 2);
    rs1 += __shfl_xor_sync(0xFFFFFFFFu, rs1, 1);
    rs1 += __shfl_xor_sync(0xFFFFFFFFu, rs1, 2);
    const float inv0 = 1.f / rs0;
    const float inv1 = 1.f / rs1;

    const int r0 = b * T_ + q0 + wid * 16 + gid;
    #pragma unroll
    for (int n = 0; n < 16; n++) {
        const int c = h * HD_ + n * 8 + tig * 2;
        const __half2 v0 = __floats2half2_rn(oacc[n][0] * inv0, oacc[n][1] * inv0);
        const __half2 v1 = __floats2half2_rn(oacc[n][2] * inv1, oacc[n][3] * inv1);
        *(__half2*)&outp[(size_t)r0 * D_ + c]       = v0;
        *(__half2*)&outp[(size_t)(r0 + 8) * D_ + c] = v1;
    }
}

// ---------------- launch ----------------
extern "C" void kernel_launch(void* const* d_in, const int* in_sizes, int n_in,
                              void* d_out, int out_size)
{
    const float* query = (const float*)d_in[0];
    const float* key   = (const float*)d_in[1];
    const float* value = (const float*)d_in[2];
    const float* wq = (const float*)d_in[4];
    const float* bq = (const float*)d_in[5];
    const float* wk = (const float*)d_in[6];
    const float* bk = (const float*)d_in[7];
    const float* wv = (const float*)d_in[8];
    const float* bv = (const float*)d_in[9];
    const float* wo = (const float*)d_in[10];
    float* out = (float*)d_out;

    __nv_bfloat16 *xqh, *xql, *xkh, *xkl, *xvh, *xvl, *wth;
    __nv_bfloat16 *qh, *ql, *kh, *kl, *vh, *vl;
    cudaGetSymbolAddress((void**)&xqh, g_xq_hi);
    cudaGetSymbolAddress((void**)&xql, g_xq_lo);
    cudaGetSymbolAddress((void**)&xkh, g_xk_hi);
    cudaGetSymbolAddress((void**)&xkl, g_xk_lo);
    cudaGetSymbolAddress((void**)&xvh, g_xv_hi);
    cudaGetSymbolAddress((void**)&xvl, g_xv_lo);
    cudaGetSymbolAddress((void**)&wth, g_wt_hi);
    cudaGetSymbolAddress((void**)&qh, g_qh);
    cudaGetSymbolAddress((void**)&ql, g_ql);
    cudaGetSymbolAddress((void**)&kh, g_kh);
    cudaGetSymbolAddress((void**)&kl, g_kl);
    cudaGetSymbolAddress((void**)&vh, g_vh);
    cudaGetSymbolAddress((void**)&vl, g_vl);

    cudaFuncSetAttribute(hmma_gemm_qkv_kernel, cudaFuncAttributeMaxDynamicSharedMemorySize, QSMEM_BYTES);
    cudaFuncSetAttribute(hmma_gemm_o_f16_kernel, cudaFuncAttributeMaxDynamicSharedMemorySize, OSMEM_BYTES);
    cudaFuncSetAttribute(attn_hmma_kernel, cudaFuncAttributeMaxDynamicSharedMemorySize, ASMEM_BYTES);

    const int M = M_ROWS;
    const int n4 = M * D_ / 4;
    const dim3 tb(32, 8);

    rope_table_kernel<<<(T_ * 64) / 256, 256>>>();
    conv_split3_f16_kernel<<<dim3((n4 + 255) / 256, 3), 256>>>(
        query, key, value,
        (__half*)xqh, (__half*)xql, (__half*)xkh, (__half*)xkl,
        (__half*)xvh, (__half*)xvl, n4);
    transpose_half_kernel<<<dim3((NQ_ * HD_) / 32, D_ / 32), tb>>>(wq, (__half*)wth, D_, NQ_ * HD_, 0);
    transpose_half_kernel<<<dim3((NKV_ * HD_) / 32, D_ / 32), tb>>>(wk, (__half*)wth, D_, NKV_ * HD_, NQ_ * HD_);
    transpose_half_kernel<<<dim3((NKV_ * HD_) / 32, D_ / 32), tb>>>(wv, (__half*)wth, D_, NKV_ * HD_, NQ_ * HD_ + NKV_ * HD_);
    hmma_gemm_qkv_kernel<<<dim3(NQKV / 128, M / 128), 256, QSMEM_BYTES>>>(
        (const __half*)xqh, (const __half*)xql, (const __half*)xkh, (const __half*)xkl,
        (const __half*)xvh, (const __half*)xvl, (const __half*)wth, bq, bk, bv,
        qh, ql, kh, kl, vh, vl);
    attn_hmma_kernel<<<dim3(T_ / 128, B_ * NQ_), 256, ASMEM_BYTES>>>(
        qh, ql, kh, kl, vh, vl, (__half*)xqh);
    transpose_half_kernel<<<dim3(D_ / 32, (NQ_ * HD_) / 32), tb>>>(wo, (__half*)wth, NQ_ * HD_, D_, 0);
    hmma_gemm_o_f16_kernel<<<dim3(D_ / 128, M / 128), 256, OSMEM_BYTES>>>(
        (const __half*)xqh, (const __half*)wth, out, M, D_, NQ_ * HD_);
}

// round 16
// speedup vs baseline: 1.0680x; 1.0680x over previous
#include <cuda_runtime.h>
#include <cuda_bf16.h>
#include <cuda_fp16.h>
#include <cstdint>
#include <math.h>

#define B_   2
#define T_   1024
#define D_   6144
#define NQ_  48
#define NKV_ 8
#define HD_  128
#define GQ_  (NQ_ / NKV_)
#define MULT_     0.08838834764831845f
#define MAX_ATTN_ 30.0f
#define M_ROWS (B_ * T_)           // 2048
#define NQKV   (NQ_ * HD_ + 2 * NKV_ * HD_)   // 8192 -> 64 n-blocks of 128
#define KBLK0  NQ_
#define VBLK0  (NQ_ + NKV_)

// ---------------- scratch (__device__ globals; no allocation) ----------------
__device__ float2 g_rope[T_ * 64];

__device__ __nv_bfloat16 g_xq_hi[(size_t)M_ROWS * D_];
__device__ __nv_bfloat16 g_xq_lo[(size_t)M_ROWS * D_];
__device__ __nv_bfloat16 g_xk_hi[(size_t)M_ROWS * D_];
__device__ __nv_bfloat16 g_xk_lo[(size_t)M_ROWS * D_];
__device__ __nv_bfloat16 g_xv_hi[(size_t)M_ROWS * D_];
__device__ __nv_bfloat16 g_xv_lo[(size_t)M_ROWS * D_];
__device__ __nv_bfloat16 g_wt_hi[(size_t)NQKV * D_];
__device__ __nv_bfloat16 g_wt_lo[(size_t)NQKV * D_];
__device__ __nv_bfloat16 g_qh[(size_t)M_ROWS * NQ_ * HD_];
__device__ __nv_bfloat16 g_ql[(size_t)M_ROWS * NQ_ * HD_];
__device__ __nv_bfloat16 g_kh[(size_t)M_ROWS * NKV_ * HD_];
__device__ __nv_bfloat16 g_kl[(size_t)M_ROWS * NKV_ * HD_];
__device__ __nv_bfloat16 g_vh[(size_t)M_ROWS * NKV_ * HD_];
__device__ __nv_bfloat16 g_vl[(size_t)M_ROWS * NKV_ * HD_];

// ---------------- rope table ----------------
__global__ void rope_table_kernel() {
    const int i = blockIdx.x * blockDim.x + threadIdx.x;
    const int t = i >> 6, j = i & 63;
    const double invf = exp(-log(10000.0) * (double)j / 64.0);
    double ph = (double)t * invf;
    const double twopi = 6.283185307179586476925286766559;
    ph -= twopi * floor(ph / twopi);
    float s, c;
    sincosf((float)ph, &s, &c);
    g_rope[i] = make_float2(c, s);
}

// ---------------- fp32 -> (hi, lo) fp16 split, 3 tensors ----------------
__global__ __launch_bounds__(256) void conv_split3_f16_kernel(
    const float* __restrict__ x0, const float* __restrict__ x1, const float* __restrict__ x2,
    __half* __restrict__ h0p, __half* __restrict__ l0p,
    __half* __restrict__ h1p, __half* __restrict__ l1p,
    __half* __restrict__ h2p, __half* __restrict__ l2p, int n4)
{
    const int i = blockIdx.x * blockDim.x + threadIdx.x;
    if (i >= n4) return;
    const float* x = (blockIdx.y == 0) ? x0 : (blockIdx.y == 1) ? x1 : x2;
    __half* hi = (blockIdx.y == 0) ? h0p : (blockIdx.y == 1) ? h1p : h2p;
    __half* lo = (blockIdx.y == 0) ? l0p : (blockIdx.y == 1) ? l1p : l2p;
    const float4 v = ((const float4*)x)[i];
    const __half h0 = __float2half_rn(v.x);
    const __half h1 = __float2half_rn(v.y);
    const __half h2 = __float2half_rn(v.z);
    const __half h3 = __float2half_rn(v.w);
    __half2* H = (__half2*)hi;
    __half2* L = (__half2*)lo;
    H[2 * i]     = __half2(h0, h1);
    H[2 * i + 1] = __half2(h2, h3);
    L[2 * i]     = __half2(__float2half_rn(v.x - __half2float(h0)),
                           __float2half_rn(v.y - __half2float(h1)));
    L[2 * i + 1] = __half2(__float2half_rn(v.z - __half2float(h2)),
                           __float2half_rn(v.w - __half2float(h3)));
}

// ---------------- W[K,N] fp32 -> Wt[N,K] fp16, row offset ----------------
__global__ void transpose_half_kernel(
    const float* __restrict__ W, __half* __restrict__ Th, int K, int N, int row_off)
{
    __shared__ float s[32][33];
    const int k0 = blockIdx.y * 32, n0 = blockIdx.x * 32;
    const int tx = threadIdx.x, ty = threadIdx.y;
    #pragma unroll
    for (int i = 0; i < 4; i++)
        s[ty + 8 * i][tx] = W[(size_t)(k0 + ty + 8 * i) * N + n0 + tx];
    __syncthreads();
    #pragma unroll
    for (int i = 0; i < 4; i++)
        Th[(size_t)(row_off + n0 + ty + 8 * i) * K + k0 + tx] =
            __float2half_rn(s[tx][ty + 8 * i]);
}

// ---------------- common MMA helpers ----------------
__device__ __forceinline__ uint32_t smem_u32(const void* p) {
    uint32_t a;
    asm("{ .reg .u64 t; cvta.to.shared.u64 t, %1; cvt.u32.u64 %0, t; }" : "=r"(a) : "l"(p));
    return a;
}
__device__ __forceinline__ void cp16(uint32_t dst, const void* src) {
    asm volatile("cp.async.cg.shared.global [%0], [%1], 16;" :: "r"(dst), "l"(src));
}
__device__ __forceinline__ void mma_bf16(float* c, const uint32_t* a, const uint32_t* b) {
    asm volatile(
        "mma.sync.aligned.m16n8k16.row.col.f32.bf16.bf16.f32 "
        "{%0,%1,%2,%3}, {%4,%5,%6,%7}, {%8,%9}, {%0,%1,%2,%3};"
        : "+f"(c[0]), "+f"(c[1]), "+f"(c[2]), "+f"(c[3])
        : "r"(a[0]), "r"(a[1]), "r"(a[2]), "r"(a[3]), "r"(b[0]), "r"(b[1]));
}
__device__ __forceinline__ void mma_f16(float* c, const uint32_t* a, const uint32_t* b) {
    asm volatile(
        "mma.sync.aligned.m16n8k16.row.col.f32.f16.f16.f32 "
        "{%0,%1,%2,%3}, {%4,%5,%6,%7}, {%8,%9}, {%0,%1,%2,%3};"
        : "+f"(c[0]), "+f"(c[1]), "+f"(c[2]), "+f"(c[3])
        : "r"(a[0]), "r"(a[1]), "r"(a[2]), "r"(a[3]), "r"(b[0]), "r"(b[1]));
}
__device__ __forceinline__ void ldsm_x4(uint32_t* r, uint32_t addr) {
    asm volatile("ldmatrix.sync.aligned.m8n8.x4.shared.b16 {%0,%1,%2,%3}, [%4];"
        : "=r"(r[0]), "=r"(r[1]), "=r"(r[2]), "=r"(r[3]) : "r"(addr));
}
__device__ __forceinline__ void ldsm_x4t(uint32_t* r, uint32_t addr) {
    asm volatile("ldmatrix.sync.aligned.m8n8.x4.trans.shared.b16 {%0,%1,%2,%3}, [%4];"
        : "=r"(r[0]), "=r"(r[1]), "=r"(r[2]), "=r"(r[3]) : "r"(addr));
}
__device__ __forceinline__ uint32_t pack_hi(float a, float b) {
    __nv_bfloat162 t(__float2bfloat16_rn(a), __float2bfloat16_rn(b));
    return *(uint32_t*)&t;
}
__device__ __forceinline__ uint32_t pack_lo(float a, float b, uint32_t hi) {
    __nv_bfloat162 h = *(__nv_bfloat162*)&hi;
    __nv_bfloat162 t(__float2bfloat16_rn(a - __bfloat162float(h.x)),
                     __float2bfloat16_rn(b - __bfloat162float(h.y)));
    return *(uint32_t*)&t;
}

#define PITCH_E   40
#define TILE_E    (128 * PITCH_E)             // 5120 halfs / 10240 B
#define QSTAGE_E  (3 * TILE_E)                // Ah, Al, B
#define QSMEM_BYTES 67584                     // max(2*QSTAGE_E*2=61440, epi 128*132*4)

// ---------------- fp16 2-term mainloop, 2-stage (R13, proven best) ----------
__device__ __forceinline__ void gemm_mainloop_2t(
    const __half* __restrict__ Ah_g, const __half* __restrict__ Al_g,
    const __half* __restrict__ B_g, int K, uint32_t sb, float acc[4][4][4])
{
    const int tid  = threadIdx.x;
    const int wid  = tid >> 5, lane = tid & 31;
    const int wm   = wid >> 2;
    const int wn   = wid & 3;
    const int a_row = ((lane >> 3) & 1) * 8 + (lane & 7);
    const int a_col = (lane >> 4) * 8;
    const int b_row = ((lane >> 4) & 1) * 8 + (lane & 7);
    const int b_col = ((lane >> 3) & 1) * 8;

    const __half* srcs[3] = { Ah_g, Al_g, B_g };
    const int nk = K / 32;

    auto load_chunk = [&](int c, int s) {
        const uint32_t sbase = sb + s * (QSTAGE_E * 2);
        #pragma unroll
        for (int t = 0; t < 3; t++) {
            #pragma unroll
            for (int j = 0; j < 2; j++) {
                const int i   = tid + 256 * j;
                const int row = i >> 2;
                const int kc  = i & 3;
                cp16(sbase + t * (TILE_E * 2) + row * (PITCH_E * 2) + kc * 16,
                     srcs[t] + (size_t)row * K + c * 32 + kc * 8);
            }
        }
    };

    load_chunk(0, 0);
    asm volatile("cp.async.commit_group;");

    for (int c = 0; c < nk; c++) {
        if (c + 1 < nk) {
            load_chunk(c + 1, (c + 1) & 1);
            asm volatile("cp.async.commit_group;");
            asm volatile("cp.async.wait_group 1;");
        } else {
            asm volatile("cp.async.wait_group 0;");
        }
        __syncthreads();

        const uint32_t Ahb = sb + (c & 1) * (QSTAGE_E * 2);
        const uint32_t Alb = Ahb + TILE_E * 2;
        const uint32_t Bb  = Ahb + 2 * TILE_E * 2;

        #pragma unroll
        for (int ks = 0; ks < 2; ks++) {
            const int k16 = ks * 16;
            uint32_t ah[4][4], al[4][4], bf[4][2];
            #pragma unroll
            for (int mf = 0; mf < 4; mf++) {
                const uint32_t off =
                    ((wm * 64 + mf * 16 + a_row) * PITCH_E + k16 + a_col) * 2;
                ldsm_x4(ah[mf], Ahb + off);
                ldsm_x4(al[mf], Alb + off);
            }
            #pragma unroll
            for (int nfp = 0; nfp < 2; nfp++) {
                const uint32_t off =
                    ((wn * 32 + nfp * 16 + b_row) * PITCH_E + k16 + b_col) * 2;
                uint32_t r[4];
                ldsm_x4(r, Bb + off);
                bf[2 * nfp][0] = r[0]; bf[2 * nfp][1] = r[1];
                bf[2 * nfp + 1][0] = r[2]; bf[2 * nfp + 1][1] = r[3];
            }
            #pragma unroll
            for (int mf = 0; mf < 4; mf++)
                #pragma unroll
                for (int nf = 0; nf < 4; nf++) {
                    mma_f16(acc[mf][nf], ah[mf], bf[nf]);
                    mma_f16(acc[mf][nf], al[mf], bf[nf]);
                }
        }
        __syncthreads();
    }
}

// ---------------- merged QKV GEMM (fp16 2-term) + fused epilogue ------------
__global__ __launch_bounds__(256) void hmma_gemm_qkv_kernel(
    const __half* __restrict__ Xqh, const __half* __restrict__ Xql,
    const __half* __restrict__ Xkh, const __half* __restrict__ Xkl,
    const __half* __restrict__ Xvh, const __half* __restrict__ Xvl,
    const __half* __restrict__ Wt,
    const float* __restrict__ bq, const float* __restrict__ bk, const float* __restrict__ bv,
    __nv_bfloat16* __restrict__ qh, __nv_bfloat16* __restrict__ ql,
    __nv_bfloat16* __restrict__ kh, __nv_bfloat16* __restrict__ kl,
    __nv_bfloat16* __restrict__ vh, __nv_bfloat16* __restrict__ vl)
{
    extern __shared__ __half smh[];
    const uint32_t sb = smem_u32(smh);
    const int tid = threadIdx.x;
    const int wid = tid >> 5, lane = tid & 31;
    const int wm = wid >> 2, wn = wid & 3;
    const int gid = lane >> 2, tig = lane & 3;
    const int m0 = blockIdx.y * 128;
    const int jb = blockIdx.x;
    const int K  = D_;

    const int region = (jb < KBLK0) ? 0 : ((jb < VBLK0) ? 1 : 2);
    const __half* Ah_g = (region == 0) ? Xqh : (region == 1) ? Xkh : Xvh;
    const __half* Al_g = (region == 0) ? Xql : (region == 1) ? Xkl : Xvl;

    float acc[4][4][4];
    #pragma unroll
    for (int i = 0; i < 4; i++)
        #pragma unroll
        for (int j = 0; j < 4; j++)
            #pragma unroll
            for (int v = 0; v < 4; v++) acc[i][j][v] = 0.f;

    gemm_mainloop_2t(Ah_g + (size_t)m0 * K, Al_g + (size_t)m0 * K,
                     Wt + (size_t)jb * 128 * K, K, sb, acc);

    const int Nreg = (region == 0) ? NQ_ * HD_ : NKV_ * HD_;
    const int n0r  = (region == 0) ? jb * 128 : (region == 1) ? (jb - KBLK0) * 128
                                              : (jb - VBLK0) * 128;
    const float* bias = (region == 0) ? bq : (region == 1) ? bk : bv;
    __nv_bfloat16* Yh = (region == 0) ? qh : (region == 1) ? kh : vh;
    __nv_bfloat16* Yl = (region == 0) ? ql : (region == 1) ? kl : vl;

    float* sepi = (float*)smh;
    __syncthreads();
    #pragma unroll
    for (int mf = 0; mf < 4; mf++) {
        const int r = wm * 64 + mf * 16 + gid;
        #pragma unroll
        for (int nf = 0; nf < 4; nf++) {
            const int col = wn * 32 + nf * 8 + 2 * tig;
            *(float2*)&sepi[r * 132 + col]       = make_float2(acc[mf][nf][0], acc[mf][nf][1]);
            *(float2*)&sepi[(r + 8) * 132 + col] = make_float2(acc[mf][nf][2], acc[mf][nf][3]);
        }
    }
    __syncthreads();
    const bool do_rope = (region < 2);
    #pragma unroll
    for (int it = 0; it < 16; it++) {
        const int idx = it * 256 + tid;
        const int r = idx >> 5, j = (idx & 31) * 2;
        const int t = (m0 + r) % T_;
        const float x1a = sepi[r * 132 + j]      + bias[n0r + j];
        const float x1b = sepi[r * 132 + j + 1]  + bias[n0r + j + 1];
        const float x2a = sepi[r * 132 + j + 64] + bias[n0r + j + 64];
        const float x2b = sepi[r * 132 + j + 65] + bias[n0r + j + 65];
        float o1a, o1b, o2a, o2b;
        if (do_rope) {
            const float2 cs0 = g_rope[t * 64 + j];
            const float2 cs1 = g_rope[t * 64 + j + 1];
            o1a = x1a * cs0.x - x2a * cs0.y;
            o1b = x1b * cs1.x - x2b * cs1.y;
            o2a = x2a * cs0.x + x1a * cs0.y;
            o2b = x2b * cs1.x + x1b * cs1.y;
        } else {
            o1a = x1a; o1b = x1b; o2a = x2a; o2b = x2b;
        }
        const size_t base = (size_t)(m0 + r) * Nreg + n0r;
        const uint32_t h1 = pack_hi(o1a, o1b), h2 = pack_hi(o2a, o2b);
        *(uint32_t*)&Yh[base + j]      = h1;
        *(uint32_t*)&Yh[base + j + 64] = h2;
        *(uint32_t*)&Yl[base + j]      = pack_lo(o1a, o1b, h1);
        *(uint32_t*)&Yl[base + j + 64] = pack_lo(o2a, o2b, h2);
    }
}

// ---------------- fp16 single-plane O-GEMM, 2-stage (R13, proven) -----------
#define OTILE_E   (128 * PITCH_E)
#define OSTAGE_E  (2 * OTILE_E)
#define OSMEM_BYTES (2 * OSTAGE_E * 2)       // 40960 B

__global__ __launch_bounds__(256) void hmma_gemm_o_f16_kernel(
    const __half* __restrict__ X, const __half* __restrict__ W,
    float* __restrict__ Yf, int M, int N, int K)
{
    extern __shared__ __half smh[];
    const uint32_t sb = smem_u32(smh);
    const int tid = threadIdx.x;
    const int wid = tid >> 5, lane = tid & 31;
    const int wm = wid >> 2, wn = wid & 3;
    const int gid = lane >> 2, tig = lane & 3;
    const int m0 = blockIdx.y * 128;
    const int n0 = blockIdx.x * 128;
    const int a_row = ((lane >> 3) & 1) * 8 + (lane & 7);
    const int a_col = (lane >> 4) * 8;
    const int b_row = ((lane >> 4) & 1) * 8 + (lane & 7);
    const int b_col = ((lane >> 3) & 1) * 8;

    const __half* Ag = X + (size_t)m0 * K;
    const __half* Bg = W + (size_t)n0 * K;

    float acc[4][4][4];
    #pragma unroll
    for (int i = 0; i < 4; i++)
        #pragma unroll
        for (int j = 0; j < 4; j++)
            #pragma unroll
            for (int v = 0; v < 4; v++) acc[i][j][v] = 0.f;

    const int nk = K / 32;

    auto load_chunk = [&](int c, int s) {
        const uint32_t sbase = sb + s * (OSTAGE_E * 2);
        #pragma unroll
        for (int j = 0; j < 2; j++) {
            const int i = tid + 256 * j;
            const int row = i >> 2;
            const int kc = i & 3;
            const size_t goff = (size_t)row * K + c * 32 + kc * 8;
            const uint32_t soff = row * (PITCH_E * 2) + kc * 16;
            cp16(sbase + soff, Ag + goff);
            cp16(sbase + OTILE_E * 2 + soff, Bg + goff);
        }
    };

    load_chunk(0, 0);
    asm volatile("cp.async.commit_group;");

    for (int c = 0; c < nk; c++) {
        if (c + 1 < nk) {
            load_chunk(c + 1, (c + 1) & 1);
            asm volatile("cp.async.commit_group;");
            asm volatile("cp.async.wait_group 1;");
        } else {
            asm volatile("cp.async.wait_group 0;");
        }
        __syncthreads();

        const uint32_t Ab = sb + (c & 1) * (OSTAGE_E * 2);
        const uint32_t Bb = Ab + OTILE_E * 2;

        #pragma unroll
        for (int ks = 0; ks < 2; ks++) {
            const int k16 = ks * 16;
            uint32_t af[4][4], bf[4][2];
            #pragma unroll
            for (int mf = 0; mf < 4; mf++) {
                const uint32_t off =
                    ((wm * 64 + mf * 16 + a_row) * PITCH_E + k16 + a_col) * 2;
                ldsm_x4(af[mf], Ab + off);
            }
            #pragma unroll
            for (int nfp = 0; nfp < 2; nfp++) {
                const uint32_t off =
                    ((wn * 32 + nfp * 16 + b_row) * PITCH_E + k16 + b_col) * 2;
                uint32_t r[4];
                ldsm_x4(r, Bb + off);
                bf[2 * nfp][0] = r[0]; bf[2 * nfp][1] = r[1];
                bf[2 * nfp + 1][0] = r[2]; bf[2 * nfp + 1][1] = r[3];
            }
            #pragma unroll
            for (int mf = 0; mf < 4; mf++)
                #pragma unroll
                for (int nf = 0; nf < 4; nf++)
                    mma_f16(acc[mf][nf], af[mf], bf[nf]);
        }
        __syncthreads();
    }

    #pragma unroll
    for (int mf = 0; mf < 4; mf++) {
        const int row = m0 + wm * 64 + mf * 16 + gid;
        #pragma unroll
        for (int nf = 0; nf < 4; nf++) {
            const int col = n0 + wn * 32 + nf * 8 + 2 * tig;
            *(float2*)&Yf[(size_t)row * N + col] =
                make_float2(acc[mf][nf][0], acc[mf][nf][1]);
            *(float2*)&Yf[(size_t)(row + 8) * N + col] =
                make_float2(acc[mf][nf][2], acc[mf][nf][3]);
        }
    }
}

// ---------------- HMMA attention (R13 structure; cp.async single-buffer) ----
#define AQ_P 136
#define ASMEM_BYTES ((2 * 128 + 4 * 64) * AQ_P * 2)   // 139264 B

__device__ __forceinline__ float softcap_exp(float s) {
    const float x = s * (MULT_ / MAX_ATTN_);
    const float e2 = __expf(2.f * x);
    const float cap = MAX_ATTN_ - __fdividef(2.f * MAX_ATTN_, e2 + 1.f);
    return __expf(cap);
}

__global__ __launch_bounds__(256) void attn_hmma_kernel(
    const __nv_bfloat16* __restrict__ gqh, const __nv_bfloat16* __restrict__ gql,
    const __nv_bfloat16* __restrict__ gkh, const __nv_bfloat16* __restrict__ gkl,
    const __nv_bfloat16* __restrict__ gvh, const __nv_bfloat16* __restrict__ gvl,
    __half* __restrict__ outp)
{
    extern __shared__ __nv_bfloat16 as2[];
    __nv_bfloat16* Qh  = as2;
    __nv_bfloat16* Ql  = Qh + 128 * AQ_P;
    const uint32_t sbA = smem_u32(as2);
    const uint32_t QhO = 0;
    const uint32_t QlO = 128 * AQ_P * 2;
    const uint32_t KhO = 2 * 128 * AQ_P * 2;
    const uint32_t KlO = KhO + 64 * AQ_P * 2;
    const uint32_t VhO = KlO + 64 * AQ_P * 2;
    const uint32_t VlO = VhO + 64 * AQ_P * 2;

    const int bh  = blockIdx.y;
    const int b   = bh / NQ_;
    const int h   = bh % NQ_;
    const int kvh = h / GQ_;
    const int q0  = blockIdx.x * 128;

    const int tid = threadIdx.x;
    const int wid = tid >> 5, lane = tid & 31;
    const int gid = lane >> 2, tig = lane & 3;
    const int a_row = ((lane >> 3) & 1) * 8 + (lane & 7);
    const int a_col = (lane >> 4) * 8;
    const int b_row = ((lane >> 4) & 1) * 8 + (lane & 7);
    const int b_col = ((lane >> 3) & 1) * 8;

    for (int i = tid; i < 128 * 16; i += 256) {
        const int row = i >> 4, c16 = (i & 15) * 8;
        const size_t src = ((size_t)(b * T_ + q0 + row)) * (NQ_ * HD_) + h * HD_ + c16;
        *(uint4*)&Qh[row * AQ_P + c16] = *(const uint4*)&gqh[src];
        *(uint4*)&Ql[row * AQ_P + c16] = *(const uint4*)&gql[src];
    }

    float oacc[16][4];
    #pragma unroll
    for (int n = 0; n < 16; n++)
        #pragma unroll
        for (int v = 0; v < 4; v++) oacc[n][v] = 0.f;
    float rs0 = 0.f, rs1 = 0.f;

    const int qg0 = q0 + wid * 16 + gid;
    const int qg1 = qg0 + 8;

    const int nkb = 2 * blockIdx.x + 2;
    for (int kb = 0; kb < nkb; kb++) {
        __syncthreads();   // all warps done reading previous K/V before overwrite
        // cp.async single-buffer load of this iteration's K/V planes
        #pragma unroll
        for (int it = 0; it < 4; it++) {
            const int i = tid + 256 * it;          // 0..1023 = 64 rows x 16 chunks
            const int row = i >> 4, c16 = (i & 15) * 8;
            const size_t src = ((size_t)(b * T_ + kb * 64 + row)) * (NKV_ * HD_) + kvh * HD_ + c16;
            const uint32_t d = (row * AQ_P + c16) * 2;
            cp16(sbA + KhO + d, gkh + src);
            cp16(sbA + KlO + d, gkl + src);
            cp16(sbA + VhO + d, gvh + src);
            cp16(sbA + VlO + d, gvl + src);
        }
        asm volatile("cp.async.commit_group;");
        asm volatile("cp.async.wait_group 0;");
        __syncthreads();

        float sacc[8][4];
        #pragma unroll
        for (int nf = 0; nf < 8; nf++)
            #pragma unroll
            for (int v = 0; v < 4; v++) sacc[nf][v] = 0.f;

        #pragma unroll
        for (int ks = 0; ks < 8; ks++) {
            uint32_t ah[4], al[4];
            const uint32_t offa = ((wid * 16 + a_row) * AQ_P + ks * 16 + a_col) * 2;
            ldsm_x4(ah, sbA + QhO + offa);
            ldsm_x4(al, sbA + QlO + offa);
            #pragma unroll
            for (int g = 0; g < 4; g++) {
                const uint32_t offb = ((g * 16 + b_row) * AQ_P + ks * 16 + b_col) * 2;
                uint32_t rh[4], rl[4];
                ldsm_x4(rh, sbA + KhO + offb);
                ldsm_x4(rl, sbA + KlO + offb);
                mma_bf16(sacc[2 * g],     ah, rh);
                mma_bf16(sacc[2 * g],     ah, rl);
                mma_bf16(sacc[2 * g],     al, rh);
                mma_bf16(sacc[2 * g + 1], ah, rh + 2);
                mma_bf16(sacc[2 * g + 1], ah, rl + 2);
                mma_bf16(sacc[2 * g + 1], al, rh + 2);
            }
        }

        uint32_t ph[8][2], pl[8][2];
        #pragma unroll
        for (int nf = 0; nf < 8; nf++) {
            const int kg = kb * 64 + nf * 8 + tig * 2;
            float p0 = (kg     <= qg0) ? softcap_exp(sacc[nf][0]) : 0.f;
            float p1 = (kg + 1 <= qg0) ? softcap_exp(sacc[nf][1]) : 0.f;
            float p2 = (kg     <= qg1) ? softcap_exp(sacc[nf][2]) : 0.f;
            float p3 = (kg + 1 <= qg1) ? softcap_exp(sacc[nf][3]) : 0.f;
            rs0 += p0 + p1;
            rs1 += p2 + p3;
            ph[nf][0] = pack_hi(p0, p1);
            ph[nf][1] = pack_hi(p2, p3);
            pl[nf][0] = pack_lo(p0, p1, ph[nf][0]);
            pl[nf][1] = pack_lo(p2, p3, ph[nf][1]);
        }

        #pragma unroll
        for (int s = 0; s < 4; s++) {
            uint32_t ah2[4] = { ph[2 * s][0], ph[2 * s][1], ph[2 * s + 1][0], ph[2 * s + 1][1] };
            uint32_t al2[4] = { pl[2 * s][0], pl[2 * s][1], pl[2 * s + 1][0], pl[2 * s + 1][1] };
            #pragma unroll
            for (int g = 0; g < 8; g++) {
                const uint32_t offv = ((s * 16 + a_row) * AQ_P + g * 16 + a_col) * 2;
                uint32_t rh[4], rl[4];
                ldsm_x4t(rh, sbA + VhO + offv);
                ldsm_x4t(rl, sbA + VlO + offv);
                mma_bf16(oacc[2 * g],     ah2, rh);
                mma_bf16(oacc[2 * g],     ah2, rl);
                mma_bf16(oacc[2 * g],     al2, rh);
                mma_bf16(oacc[2 * g + 1], ah2, rh + 2);
                mma_bf16(oacc[2 * g + 1], ah2, rl + 2);
                mma_bf16(oacc[2 * g + 1], al2, rh + 2);
            }
        }
    }

    rs0 += __shfl_xor_sync(0xFFFFFFFFu, rs0, 1);
    rs0 += __shfl_xor_sync(0xFFFFFFFFu, rs0, 2);
    rs1 += __shfl_xor_sync(0xFFFFFFFFu, rs1, 1);
    rs1 += __shfl_xor_sync(0xFFFFFFFFu, rs1, 2);
    const float inv0 = 1.f / rs0;
    const float inv1 = 1.f / rs1;

    const int r0 = b * T_ + q0 + wid * 16 + gid;
    #pragma unroll
    for (int n = 0; n < 16; n++) {
        const int c = h * HD_ + n * 8 + tig * 2;
        const __half2 v0 = __floats2half2_rn(oacc[n][0] * inv0, oacc[n][1] * inv0);
        const __half2 v1 = __floats2half2_rn(oacc[n][2] * inv1, oacc[n][3] * inv1);
        *(__half2*)&outp[(size_t)r0 * D_ + c]       = v0;
        *(__half2*)&outp[(size_t)(r0 + 8) * D_ + c] = v1;
    }
}

// ---------------- launch ----------------
extern "C" void kernel_launch(void* const* d_in, const int* in_sizes, int n_in,
                              void* d_out, int out_size)
{
    const float* query = (const float*)d_in[0];
    const float* key   = (const float*)d_in[1];
    const float* value = (const float*)d_in[2];
    const float* wq = (const float*)d_in[4];
    const float* bq = (const float*)d_in[5];
    const float* wk = (const float*)d_in[6];
    const float* bk = (const float*)d_in[7];
    const float* wv = (const float*)d_in[8];
    const float* bv = (const float*)d_in[9];
    const float* wo = (const float*)d_in[10];
    float* out = (float*)d_out;

    __nv_bfloat16 *xqh, *xql, *xkh, *xkl, *xvh, *xvl, *wth;
    __nv_bfloat16 *qh, *ql, *kh, *kl, *vh, *vl;
    cudaGetSymbolAddress((void**)&xqh, g_xq_hi);
    cudaGetSymbolAddress((void**)&xql, g_xq_lo);
    cudaGetSymbolAddress((void**)&xkh, g_xk_hi);
    cudaGetSymbolAddress((void**)&xkl, g_xk_lo);
    cudaGetSymbolAddress((void**)&xvh, g_xv_hi);
    cudaGetSymbolAddress((void**)&xvl, g_xv_lo);
    cudaGetSymbolAddress((void**)&wth, g_wt_hi);
    cudaGetSymbolAddress((void**)&qh, g_qh);
    cudaGetSymbolAddress((void**)&ql, g_ql);
    cudaGetSymbolAddress((void**)&kh, g_kh);
    cudaGetSymbolAddress((void**)&kl, g_kl);
    cudaGetSymbolAddress((void**)&vh, g_vh);
    cudaGetSymbolAddress((void**)&vl, g_vl);

    cudaFuncSetAttribute(hmma_gemm_qkv_kernel, cudaFuncAttributeMaxDynamicSharedMemorySize, QSMEM_BYTES);
    cudaFuncSetAttribute(hmma_gemm_o_f16_kernel, cudaFuncAttributeMaxDynamicSharedMemorySize, OSMEM_BYTES);
    cudaFuncSetAttribute(attn_hmma_kernel, cudaFuncAttributeMaxDynamicSharedMemorySize, ASMEM_BYTES);

    const int M = M_ROWS;
    const int n4 = M * D_ / 4;
    const dim3 tb(32, 8);

    rope_table_kernel<<<(T_ * 64) / 256, 256>>>();
    conv_split3_f16_kernel<<<dim3((n4 + 255) / 256, 3), 256>>>(
        query, key, value,
        (__half*)xqh, (__half*)xql, (__half*)xkh, (__half*)xkl,
        (__half*)xvh, (__half*)xvl, n4);
    transpose_half_kernel<<<dim3((NQ_ * HD_) / 32, D_ / 32), tb>>>(wq, (__half*)wth, D_, NQ_ * HD_, 0);
    transpose_half_kernel<<<dim3((NKV_ * HD_) / 32, D_ / 32), tb>>>(wk, (__half*)wth, D_, NKV_ * HD_, NQ_ * HD_);
    transpose_half_kernel<<<dim3((NKV_ * HD_) / 32, D_ / 32), tb>>>(wv, (__half*)wth, D_, NKV_ * HD_, NQ_ * HD_ + NKV_ * HD_);
    hmma_gemm_qkv_kernel<<<dim3(NQKV / 128, M / 128), 256, QSMEM_BYTES>>>(
        (const __half*)xqh, (const __half*)xql, (const __half*)xkh, (const __half*)xkl,
        (const __half*)xvh, (const __half*)xvl, (const __half*)wth, bq, bk, bv,
        qh, ql, kh, kl, vh, vl);
    attn_hmma_kernel<<<dim3(T_ / 128, B_ * NQ_), 256, ASMEM_BYTES>>>(
        qh, ql, kh, kl, vh, vl, (__half*)xqh);
    transpose_half_kernel<<<dim3(D_ / 32, (NQ_ * HD_) / 32), tb>>>(wo, (__half*)wth, NQ_ * HD_, D_, 0);
    hmma_gemm_o_f16_kernel<<<dim3(D_ / 128, M / 128), 256, OSMEM_BYTES>>>(
        (const __half*)xqh, (const __half*)wth, out, M, D_, NQ_ * HD_);
}